// round 2
// baseline (speedup 1.0000x reference)
#include <cuda_runtime.h>
#include <cuda_bf16.h>

// Variable-length prefix-mean pooling.
// features [128, 1024, 2048] f32, lengths [128] i32 (<=0 -> full L), out [128, 2048] f32.
#define PB 128
#define PL 1024
#define PD 2048

#define BLOCK_THREADS 256
#define ROW_SPLITS 16
#define ROWS_PER_SPLIT (PL / ROW_SPLITS)   // 64
// Each thread owns TWO float4 columns: d4 and d4+256 (covers all 512 float4s of a row).
#define COL_STRIDE4 256                    // float4 units between the two streams

__global__ void avgpool_var_kernel(const float* __restrict__ feat,
                                   const int* __restrict__ lengths,
                                   float* __restrict__ out) {
    const int b = blockIdx.y;
    const int len = lengths[b];
    const int eff = (len > 0) ? len : PL;

    const int r0 = blockIdx.x * ROWS_PER_SPLIT;
    if (r0 >= eff) return;
    const int nrows = min(ROWS_PER_SPLIT, eff - r0);

    const int d4 = threadIdx.x;                       // 0..255
    const float4* __restrict__ fp = (const float4*)feat;
    const size_t row_stride4 = PD / 4;                // 512
    size_t base = ((size_t)b * PL + r0) * row_stride4;

    float4 acc0 = make_float4(0.f, 0.f, 0.f, 0.f);
    float4 acc1 = make_float4(0.f, 0.f, 0.f, 0.f);

    #pragma unroll 4
    for (int r = 0; r < nrows; ++r) {
        size_t i = base + (size_t)r * row_stride4;
        float4 v0 = __ldcs(&fp[i + d4]);
        float4 v1 = __ldcs(&fp[i + d4 + COL_STRIDE4]);
        acc0.x += v0.x; acc0.y += v0.y; acc0.z += v0.z; acc0.w += v0.w;
        acc1.x += v1.x; acc1.y += v1.y; acc1.z += v1.z; acc1.w += v1.w;
    }

    const float inv = 1.0f / (float)eff;
    float* o0 = out + (size_t)b * PD + (size_t)d4 * 4;
    float* o1 = o0 + COL_STRIDE4 * 4;
    atomicAdd(o0 + 0, acc0.x * inv);
    atomicAdd(o0 + 1, acc0.y * inv);
    atomicAdd(o0 + 2, acc0.z * inv);
    atomicAdd(o0 + 3, acc0.w * inv);
    atomicAdd(o1 + 0, acc1.x * inv);
    atomicAdd(o1 + 1, acc1.y * inv);
    atomicAdd(o1 + 2, acc1.z * inv);
    atomicAdd(o1 + 3, acc1.w * inv);
}

extern "C" void kernel_launch(void* const* d_in, const int* in_sizes, int n_in,
                              void* d_out, int out_size) {
    const float* feat    = (const float*)d_in[0];
    const int*   lengths = (const int*)d_in[1];
    float*       out     = (float*)d_out;

    cudaMemsetAsync(out, 0, (size_t)out_size * sizeof(float));

    dim3 grid(ROW_SPLITS, PB);
    dim3 block(BLOCK_THREADS);
    avgpool_var_kernel<<<grid, block>>>(feat, lengths, out);
}